// round 5
// baseline (speedup 1.0000x reference)
#include <cuda_runtime.h>
#include <cstdint>

// Sliding-window unfold: out[b, i, j] = x[b, i + j]
//   x:   [128, 8192] f32,  out: [128, 8162, 31] f32
//
// 4-row-group formulation: 4 consecutive output rows = 124 floats = 31 float4s,
// and the source window advances exactly +4 floats per group. Rows total
// 1,044,736 = 4 * 261,184 groups (exact). One warp-iteration = one group:
// lane k (<31) writes float4 k from source offsets c(e) = e - 30*(e/31),
// e = 4k..4k+3 -- compile-time per lane. Pairs are contiguous & 8B aligned
// (S0 = 4g + 30b is even) => 2x LDG.64 per lane; only lanes 7 and 23 have a
// row break inside a pair -> one predicated LDG.32 patch. Batch-straddling
// groups (64 of 261k) take a generic per-element path.

static constexpr unsigned Wc   = 31u;
static constexpr unsigned NWc  = 8162u;            // rows per batch
static constexpr unsigned Lc   = 8192u;
static constexpr unsigned RT   = 128u * NWc;       // 1,044,736 rows
static constexpr unsigned NG   = RT / 4u;          // 261,184 groups
static constexpr unsigned GPW  = 32u;              // groups per warp
static constexpr unsigned NWARPS = (NG + GPW - 1u) / GPW;   // 8162
static constexpr int THREADS = 256;                // 8 warps/block

__global__ __launch_bounds__(THREADS)
void unfold_group_kernel(const float* __restrict__ x, float4* __restrict__ out4) {
    unsigned warp_gid = blockIdx.x * (THREADS / 32) + (threadIdx.x >> 5);
    if (warp_gid >= NWARPS) return;
    unsigned lane = threadIdx.x & 31u;

    unsigned g0   = warp_gid * GPW;
    unsigned gend = min(g0 + GPW, NG);
    int nIter = (int)(gend - g0);

    // ---- per-lane compile-time-ish constants (prologue only) ----
    unsigned e0 = lane * 4u;
    bool active = (lane < 31u);
    unsigned d_[4], c_[4];
#pragma unroll
    for (int m = 0; m < 4; ++m) {
        unsigned e = e0 + (unsigned)m;
        unsigned d = e / 31u;
        d_[m] = d;
        c_[m] = e - 30u * d;
    }
    bool p7  = (lane == 7u);    // half1 broken: v3 = x[S0 + 1]
    bool p23 = (lane == 23u);   // half0 broken: v1 = x[S0 + 3]
    bool pp  = p7 | p23;
    unsigned opatch = p7 ? 1u : 3u;

    // ---- group / batch state ----
    unsigned r0 = g0 * 4u;                  // first row of current group
    unsigned b  = r0 / NWc;                 // batch
    unsigned Bn = (b + 1u) * NWc;           // next batch start row
    unsigned S0 = b * Lc + (r0 - b * NWc);  // source base = r0 + 30*b

    const float*  P  = x + S0;
    const float2* A0 = (const float2*)(P + c_[0]);
    const float2* A1 = (const float2*)(P + c_[2]);
    const float*  AP = P + opatch;
    float4*       D  = out4 + (size_t)g0 * 31u + lane;

#pragma unroll 4
    for (int it = 0; it < nIter; ++it) {
        if (r0 + 3u < Bn) {
            // fast path: whole group inside batch b
            if (active) {
                float2 h0 = __ldg(A0);
                float2 h1 = __ldg(A1);
                float v0 = h0.x, v1 = h0.y, v2 = h1.x, v3 = h1.y;
                if (pp) {
                    float t = __ldg(AP);
                    v3 = p7  ? t : v3;
                    v1 = p23 ? t : v1;
                }
                *D = make_float4(v0, v1, v2, v3);
            }
        } else {
            // generic path: group straddles a batch boundary (rare)
            if (active) {
                float v[4];
#pragma unroll
                for (int m = 0; m < 4; ++m) {
                    unsigned row = r0 + d_[m];
                    unsigned src = S0 + c_[m] + ((row >= Bn) ? 30u : 0u);
                    v[m] = __ldg(x + src);
                }
                *D = make_float4(v[0], v[1], v[2], v[3]);
            }
        }
        // ---- advance one group: src +4 floats, dst +31 float4 ----
        r0 += 4u;
        S0 += 4u;
        A0 += 2; A1 += 2; AP += 4;
        D  += 31;
        if (r0 >= Bn) {                      // entered a new batch: src +30 extra
            b  += 1u;
            Bn += NWc;
            S0 += 30u;
            A0 = (const float2*)((const float*)A0 + 30);
            A1 = (const float2*)((const float*)A1 + 30);
            AP += 30;
        }
    }
}

extern "C" void kernel_launch(void* const* d_in, const int* in_sizes, int n_in,
                              void* d_out, int out_size) {
    const float* x = (const float*)d_in[0];
    (void)in_sizes; (void)n_in; (void)out_size;

    unsigned blocks = (NWARPS + (THREADS / 32) - 1u) / (THREADS / 32);   // 1021
    unfold_group_kernel<<<blocks, THREADS>>>(x, (float4*)d_out);
}

// round 7
// speedup vs baseline: 1.0748x; 1.0748x over previous
#include <cuda_runtime.h>
#include <cstdint>

// Sliding-window unfold: out[b, i, j] = x[b, i + j]
//   x: [128, 8192] f32, out: [128, 8162, 31] f32
//
// Two-phase tile kernel.
//   Tile  = 128 output rows = 3968 floats = 992 float4s.
//   Grid  = RT / 128 = 8162 blocks (exact; 992 * 8162 = N4 exact, no tails).
// Phase 1 (fill):  warp w stages rows [w*16, w*16+16): lane j<31 does one
//   LDG x[r + 30*b + j] (31 consecutive floats, broadcast-friendly) + one
//   conflict-free STS into the tile at OUTPUT layout [row*31 + j].
//   The at-most-one batch boundary per tile is a warp-uniform select.
// Phase 2 (drain): tile is already output-ordered -> pure LDS.128 + STG.128,
//   thread t <-> float4 t, perfectly coalesced.

static constexpr unsigned NWc = 8162u;              // rows per batch
static constexpr unsigned RT  = 128u * NWc;         // 1,044,736 rows
static constexpr int ROWS_PER_TILE = 128;
static constexpr int TILE_FLOATS   = ROWS_PER_TILE * 31;   // 3968
static constexpr int TILE_F4       = TILE_FLOATS / 4;      // 992
static constexpr int THREADS       = 256;
static constexpr unsigned NBLOCKS  = RT / ROWS_PER_TILE;   // 8162 (exact)

__global__ __launch_bounds__(THREADS)
void unfold_tile_kernel(const float* __restrict__ x, float4* __restrict__ out4) {
    __shared__ float tile[TILE_FLOATS];

    const unsigned R0 = blockIdx.x * (unsigned)ROWS_PER_TILE;  // first row
    const unsigned b0 = R0 / NWc;                 // batch of first row
    const unsigned Bn = (b0 + 1u) * NWc;          // first row of next batch

    const unsigned warp = threadIdx.x >> 5;
    const unsigned lane = threadIdx.x & 31u;

    // ---- Phase 1: fill 16 rows per warp ----
    if (lane < 31u) {
        unsigned r = R0 + warp * 16u;
        const float* src = x + (r + 30u * b0 + lane);
        float*       dst = tile + (warp * 16u) * 31u + lane;
#pragma unroll
        for (int i = 0; i < 16; ++i) {
            // row r: batch = b0 + (r >= Bn); src shifts +30 past the boundary
            const float* s = src + ((r >= Bn) ? 30u : 0u);
            *dst = __ldg(s);
            dst += 31; src += 1; r += 1;
        }
    }
    __syncthreads();

    // ---- Phase 2: vectorized drain, perfectly coalesced ----
    const float4* t4 = (const float4*)tile;
    float4* obase = out4 + (size_t)blockIdx.x * TILE_F4;
#pragma unroll
    for (int k = 0; k < 4; ++k) {
        unsigned idx = threadIdx.x + (unsigned)k * THREADS;
        if (idx < (unsigned)TILE_F4)
            obase[idx] = t4[idx];
    }
}

extern "C" void kernel_launch(void* const* d_in, const int* in_sizes, int n_in,
                              void* d_out, int out_size) {
    const float* x = (const float*)d_in[0];
    (void)in_sizes; (void)n_in; (void)out_size;

    unfold_tile_kernel<<<NBLOCKS, THREADS>>>(x, (float4*)d_out);
}

// round 9
// speedup vs baseline: 1.1631x; 1.0822x over previous
#include <cuda_runtime.h>
#include <cstdint>

// Sliding-window unfold: out[b, i, j] = x[b, i + j]
//   x:   [128, 8192] f32,  out: [128, 8162, 31] f32
//
// R4 structure (best so far), tuned:
//  - block stages its entire source footprint (<= 352 consecutive floats)
//    in smem, then each thread emits 8 float4s (perfectly coalesced STG.128)
//    using 4 broadcast-friendly LDS + selects per float4.
//  - per-iteration index update uses 1024 = 33*31 + 1:
//      j += 1; s += 34; if (j==31){j=0; s-=30;}   (+ rare batch fixup)
//    so only the first float4 of each thread pays real divisions.

static constexpr unsigned Wc     = 31u;
static constexpr unsigned NWc    = 8162u;
static constexpr unsigned PER_B  = Wc * NWc;           // 253022
static constexpr unsigned TOTALc = 128u * PER_B;       // 32386816
static constexpr unsigned N4     = TOTALc / 4u;        // 8096704
static constexpr unsigned XN     = 128u * 8192u;       // input elements

static constexpr int THREADS      = 256;
static constexpr int F4_PER_T     = 8;
static constexpr int F4_PER_BLOCK = THREADS * F4_PER_T;   // 2048
static constexpr unsigned L_PER_BLOCK = F4_PER_BLOCK * 4; // 8192
static constexpr int SPAN = 352;   // src footprint: ~(8192-30*264) + 33 + 30 + pad

__global__ __launch_bounds__(THREADS)
void unfold_smem8_kernel(const float* __restrict__ x, float4* __restrict__ out) {
    __shared__ float win[SPAN];

    unsigned l0 = blockIdx.x * L_PER_BLOCK;
    unsigned g0 = l0 / Wc;
    unsigned b0 = g0 / NWc;
    unsigned s0 = g0 + 30u * b0;           // absolute src idx of window base

    // Stage the block's source footprint (<= 1408 B)
    for (unsigned i = threadIdx.x; i < (unsigned)SPAN; i += THREADS) {
        unsigned gi = s0 + i;
        win[i] = (gi < XN) ? __ldg(x + gi) : 0.0f;
    }
    __syncthreads();

    // Per-thread initial algebra (the only divisions this thread does)
    unsigned f = l0 / 4u + threadIdx.x;
    unsigned l = f * 4u;
    unsigned g = l / Wc;
    unsigned j = l - g * Wc;
    unsigned b = g / NWc;
    unsigned s = (g + j + 30u * b) - s0;   // relative src of element 0
    unsigned nextB = (b + 1u) * PER_B;

#pragma unroll
    for (int m = 0; m < F4_PER_T; ++m) {
        if (f < N4) {
            unsigned w = Wc - j;               // row start at k >= w (w >= 1)
            if (nextB - l < 4u) w = 4u;        // batch boundary: src continues
            float v0 = win[s];
            float v1 = win[s + 1u - ((1u >= w) ? 30u : 0u)];
            float v2 = win[s + 2u - ((2u >= w) ? 30u : 0u)];
            float v3 = win[s + 3u - ((3u >= w) ? 30u : 0u)];
            out[f] = make_float4(v0, v1, v2, v3);
        }
        // advance by 256 float4s = 1024 l  (1024 = 33*31 + 1)
        f += THREADS;
        l += 1024u;
        j += 1u; s += 34u;
        if (j == Wc) { j = 0u; s -= 30u; }
        if (l >= nextB) { s += 30u; nextB += PER_B; }
    }
}

extern "C" void kernel_launch(void* const* d_in, const int* in_sizes, int n_in,
                              void* d_out, int out_size) {
    const float* x = (const float*)d_in[0];
    (void)in_sizes; (void)n_in; (void)out_size;

    unsigned blocks = (N4 + F4_PER_BLOCK - 1) / F4_PER_BLOCK;   // 3954
    unfold_smem8_kernel<<<blocks, THREADS>>>(x, (float4*)d_out);
}

// round 10
// speedup vs baseline: 1.2796x; 1.1001x over previous
#include <cuda_runtime.h>
#include <cstdint>

// Sliding-window unfold: out[b, i, j] = x[b, i + j]
//   x:   [128, 8192] f32,  out: [128, 8162, 31] f32
//
// R4 structure (best measured: 20.5us) with ONE change: output stores use
// streaming cache policy (st.global.cs). The 129.5MB output stream slightly
// exceeds L2 (126MB); evict-first stores reduce L2 allocation churn and keep
// x's 4MB resident across the timed replay loop.

static constexpr unsigned Wc     = 31u;
static constexpr unsigned NWc    = 8162u;
static constexpr unsigned PER_B  = Wc * NWc;           // 253022
static constexpr unsigned TOTALc = 128u * PER_B;       // 32386816
static constexpr unsigned N4     = TOTALc / 4u;        // 8096704
static constexpr unsigned XN     = 128u * 8192u;       // input elements

static constexpr int THREADS      = 256;
static constexpr int F4_PER_T     = 6;
static constexpr int F4_PER_BLOCK = THREADS * F4_PER_T;   // 1536
static constexpr unsigned L_PER_BLOCK = F4_PER_BLOCK * 4; // 6144
static constexpr int SPAN = 260;   // max src footprint per block

__global__ __launch_bounds__(THREADS)
void unfold_smem_cs_kernel(const float* __restrict__ x, float4* __restrict__ out) {
    __shared__ float win[SPAN];

    unsigned l0 = blockIdx.x * L_PER_BLOCK;
    unsigned g0 = l0 / Wc;
    unsigned b0 = g0 / NWc;
    unsigned s0 = g0 + 30u * b0;           // absolute src idx of window base

    // Stage the block's source footprint (<= 1040 B)
    for (unsigned i = threadIdx.x; i < (unsigned)SPAN; i += THREADS) {
        unsigned gi = s0 + i;
        win[i] = (gi < XN) ? __ldg(x + gi) : 0.0f;
    }
    __syncthreads();

    // Per-thread initial algebra (the only divisions this thread does)
    unsigned f = l0 / 4u + threadIdx.x;
    unsigned l = f * 4u;
    unsigned g = l / Wc;
    unsigned j = l - g * Wc;
    unsigned b = g / NWc;
    unsigned s = (g + j + 30u * b) - s0;   // relative src of element 0
    unsigned nextB = (b + 1u) * PER_B;

#pragma unroll
    for (int m = 0; m < F4_PER_T; ++m) {
        if (f < N4) {
            unsigned w = Wc - j;               // row start at k >= w (w >= 1)
            if (nextB - l < 4u) w = 4u;        // batch boundary: src continues
            float v0 = win[s];
            float v1 = win[s + 1u - ((1u >= w) ? 30u : 0u)];
            float v2 = win[s + 2u - ((2u >= w) ? 30u : 0u)];
            float v3 = win[s + 3u - ((3u >= w) ? 30u : 0u)];
            __stcs(&out[f], make_float4(v0, v1, v2, v3));   // st.global.cs.v4
        }
        // advance by 256 float4s = 1024 l  (1024 = 33*31 + 1)
        f += THREADS;
        l += 1024u;
        j += 1u; s += 34u;
        if (j == Wc) { j = 0u; s -= 30u; }
        if (l >= nextB) { s += 30u; nextB += PER_B; }
    }
}

extern "C" void kernel_launch(void* const* d_in, const int* in_sizes, int n_in,
                              void* d_out, int out_size) {
    const float* x = (const float*)d_in[0];
    (void)in_sizes; (void)n_in; (void)out_size;

    unsigned blocks = (N4 + F4_PER_BLOCK - 1) / F4_PER_BLOCK;   // 5272
    unfold_smem_cs_kernel<<<blocks, THREADS>>>(x, (float4*)d_out);
}

// round 13
// speedup vs baseline: 1.3031x; 1.0184x over previous
#include <cuda_runtime.h>
#include <cstdint>

// Sliding-window unfold: out[b, i, j] = x[b, i + j]
//   x:   [128, 8192] f32,  out: [128, 8162, 31] f32
//
// R9 winner (smem window + incremental index algebra + streaming stores),
// retuned to 512-thread blocks: halves the per-byte cost of the smem fill,
// prologue divisions and barrier. Per-iteration stride is 512*4 = 2048 l;
// 2048 mod 31 == 2 so the recurrence is j += 2; s += 68; wrap(-30).

static constexpr unsigned Wc     = 31u;
static constexpr unsigned NWc    = 8162u;
static constexpr unsigned PER_B  = Wc * NWc;           // 253022
static constexpr unsigned TOTALc = 128u * PER_B;       // 32386816
static constexpr unsigned N4     = TOTALc / 4u;        // 8096704
static constexpr unsigned XN     = 128u * 8192u;       // input elements

static constexpr int THREADS      = 512;
static constexpr int F4_PER_T     = 6;
static constexpr int F4_PER_BLOCK = THREADS * F4_PER_T;   // 3072
static constexpr unsigned L_PER_BLOCK = F4_PER_BLOCK * 4; // 12288
// src footprint: rows spanned (<=397) + window tail 30 + batch jump 30 + pad
static constexpr int SPAN = 512;

__global__ __launch_bounds__(THREADS)
void unfold_smem_cs512_kernel(const float* __restrict__ x, float4* __restrict__ out) {
    __shared__ float win[SPAN];

    unsigned l0 = blockIdx.x * L_PER_BLOCK;
    unsigned g0 = l0 / Wc;
    unsigned b0 = g0 / NWc;
    unsigned s0 = g0 + 30u * b0;           // absolute src idx of window base

    // Stage the block's source footprint (<= 2 KB)
    for (unsigned i = threadIdx.x; i < (unsigned)SPAN; i += THREADS) {
        unsigned gi = s0 + i;
        win[i] = (gi < XN) ? __ldg(x + gi) : 0.0f;
    }
    __syncthreads();

    // Per-thread initial algebra (the only divisions this thread does)
    unsigned f = l0 / 4u + threadIdx.x;
    unsigned l = f * 4u;
    unsigned g = l / Wc;
    unsigned j = l - g * Wc;
    unsigned b = g / NWc;
    unsigned s = (g + j + 30u * b) - s0;   // relative src of element 0
    unsigned nextB = (b + 1u) * PER_B;

#pragma unroll
    for (int m = 0; m < F4_PER_T; ++m) {
        if (f < N4) {
            unsigned w = Wc - j;               // row start at k >= w (w >= 1)
            if (nextB - l < 4u) w = 4u;        // batch boundary: src continues
            float v0 = win[s];
            float v1 = win[s + 1u - ((1u >= w) ? 30u : 0u)];
            float v2 = win[s + 2u - ((2u >= w) ? 30u : 0u)];
            float v3 = win[s + 3u - ((3u >= w) ? 30u : 0u)];
            __stcs(&out[f], make_float4(v0, v1, v2, v3));   // streaming store
        }
        // advance by 512 float4s = 2048 l  (2048 = 66*31 + 2)
        f += THREADS;
        l += 2048u;
        j += 2u; s += 68u;
        if (j >= Wc) { j -= Wc; s -= 30u; }
        if (l >= nextB) { s += 30u; nextB += PER_B; }
    }
}

extern "C" void kernel_launch(void* const* d_in, const int* in_sizes, int n_in,
                              void* d_out, int out_size) {
    const float* x = (const float*)d_in[0];
    (void)in_sizes; (void)n_in; (void)out_size;

    unsigned blocks = (N4 + F4_PER_BLOCK - 1) / F4_PER_BLOCK;   // 2636
    unfold_smem_cs512_kernel<<<blocks, THREADS>>>(x, (float4*)d_out);
}